// round 9
// baseline (speedup 1.0000x reference)
#include <cuda_runtime.h>
#include <cuda_fp16.h>
#include <cstdint>
#include <math.h>

// ---------------------------------------------------------------------------
// Problem constants
// ---------------------------------------------------------------------------
#define BB     2
#define CC     64
#define HH     256
#define WW     256
#define HEADS  2
#define HD     32
#define ROWS   4
#define PP     (HH / ROWS)      // 64 windows per image
#define NN     (ROWS * WW)      // 1024 tokens per window
#define NWIN   (BB * PP)        // 128 windows
#define NWH    (NWIN * HEADS)   // 256 window-heads

#define SCALE   0.17677669529663687f   // 1/sqrt(32)
#define LOG2E   1.4426950408889634f

// ---------------------------------------------------------------------------
// Scratch: q,k,v fp16 [wh][n][d] token-major (q pre-scaled by SCALE*LOG2E)
// ---------------------------------------------------------------------------
__device__ __half g_qh[(size_t)NWH * NN * HD];
__device__ __half g_kh[(size_t)NWH * NN * HD];
__device__ __half g_vh[(size_t)NWH * NN * HD];

__device__ __forceinline__ uint32_t smem_u32(const void* p) {
    uint32_t a;
    asm("{ .reg .u64 t; cvta.to.shared.u64 t, %1; cvt.u32.u64 %0, t; }" : "=r"(a) : "l"(p));
    return a;
}

#define LDSM_X4(r0, r1, r2, r3, addr) \
    asm volatile("ldmatrix.sync.aligned.m8n8.x4.shared.b16 {%0,%1,%2,%3}, [%4];" \
                 : "=r"(r0), "=r"(r1), "=r"(r2), "=r"(r3) : "r"(addr))
#define LDSM_X4_T(r0, r1, r2, r3, addr) \
    asm volatile("ldmatrix.sync.aligned.m8n8.x4.trans.shared.b16 {%0,%1,%2,%3}, [%4];" \
                 : "=r"(r0), "=r"(r1), "=r"(r2), "=r"(r3) : "r"(addr))
#define MMA_16816(d, a0, a1, a2, a3, b0, b1) \
    asm volatile("mma.sync.aligned.m16n8k16.row.col.f32.f16.f16.f32 " \
                 "{%0,%1,%2,%3}, {%4,%5,%6,%7}, {%8,%9}, {%0,%1,%2,%3};" \
                 : "+f"((d)[0]), "+f"((d)[1]), "+f"((d)[2]), "+f"((d)[3]) \
                 : "r"(a0), "r"(a1), "r"(a2), "r"(a3), "r"(b0), "r"(b1))
#define CP_ASYNC16(dst, src) \
    asm volatile("cp.async.ca.shared.global [%0], [%1], 16;" :: "r"(dst), "l"(src))
#define CP_COMMIT()  asm volatile("cp.async.commit_group;" ::: "memory")
#define CP_WAIT0()   asm volatile("cp.async.wait_group 0;" ::: "memory")

__device__ __forceinline__ uint32_t exp2_h2(float hi, float lo) {
    uint32_t t;
    asm("{\n\t.reg .b32 u;\n\tcvt.rn.f16x2.f32 u, %1, %2;\n\tex2.approx.f16x2 %0, u;\n\t}"
        : "=r"(t) : "f"(hi), "f"(lo));
    return t;
}

// ---------------------------------------------------------------------------
// Kernel 1: window-gather + QKV projection, tensor-core GEMM.
// Grid 1024 = (b, h, half-row).  Block 256 = 8 warps; warp owns 16 tokens.
// ---------------------------------------------------------------------------
#define XSTR 72

__global__ __launch_bounds__(256, 2) void qkv_kernel(
    const float* __restrict__ x,
    const float* __restrict__ Wq,
    const float* __restrict__ Wk,
    const float* __restrict__ Wv)
{
    __shared__ __align__(16) __half smX[128 * XSTR];      // 18432 B
    __shared__ __align__(16) __half smW[3 * CC * XSTR];   // 27648 B

    const int blk = blockIdx.x;
    const int b = blk >> 9;
    const int h = (blk >> 1) & 255;
    const int half = blk & 1;
    const int w0 = half * 128;
    const int tid = threadIdx.x;
    const int wid = tid >> 5;
    const int lane = tid & 31;

    {
        const int tk = tid & 127;
        const int c0 = (tid >> 7) * 32;
        const size_t base = ((size_t)(b * CC + c0) * HH + h) * WW + w0 + tk;
#pragma unroll
        for (int c = 0; c < 32; c += 2) {
            float f0 = x[base + (size_t)c * (HH * WW)];
            float f1 = x[base + (size_t)(c + 1) * (HH * WW)];
            *(__half2*)&smX[tk * XSTR + c0 + c] = __floats2half2_rn(f0, f1);
        }
    }
    {
        const float qs = SCALE * LOG2E;
        for (int i = tid; i < 3 * CC * CC; i += 256) {
            const int m = i >> 12, j = (i >> 6) & 63, c = i & 63;
            const float* Wm = (m == 0) ? Wq : (m == 1) ? Wk : Wv;
            const float sc = (m == 0) ? qs : 1.f;
            smW[(m * CC + j) * XSTR + c] = __float2half(Wm[j * CC + c] * sc);
        }
    }
    __syncthreads();

    const uint32_t smXu = smem_u32(smX);
    const uint32_t smWu = smem_u32(smW);

    uint32_t aR[4][4];
#pragma unroll
    for (int kt = 0; kt < 4; kt++) {
        uint32_t ad = smXu + (uint32_t)(wid * 16 + (lane & 15)) * (XSTR * 2)
                    + (uint32_t)kt * 32 + (uint32_t)(lane >> 4) * 16;
        LDSM_X4(aR[kt][0], aR[kt][1], aR[kt][2], aR[kt][3], ad);
    }

    const int p = h >> 2, r = h & 3;
    const int win = b * PP + p;
    const int n0 = r * WW;
    const int grp = lane >> 2;
    const int w = w0 + wid * 16 + grp;

    __half* gdst[3] = {g_qh, g_kh, g_vh};

#pragma unroll 1
    for (int m = 0; m < 3; m++) {
        float acc[8][4];
#pragma unroll
        for (int j = 0; j < 8; j++)
            acc[j][0] = acc[j][1] = acc[j][2] = acc[j][3] = 0.f;

#pragma unroll
        for (int j = 0; j < 8; j++) {
            uint32_t b0, b1, b2, b3, c0, c1, c2, c3;
            const uint32_t wad = smWu + (uint32_t)(m * CC + j * 8 + (lane & 7)) * (XSTR * 2)
                               + (uint32_t)(lane >> 3) * 16;
            LDSM_X4(b0, b1, b2, b3, wad);
            LDSM_X4(c0, c1, c2, c3, wad + 64);
            MMA_16816(acc[j], aR[0][0], aR[0][1], aR[0][2], aR[0][3], b0, b1);
            MMA_16816(acc[j], aR[1][0], aR[1][1], aR[1][2], aR[1][3], b2, b3);
            MMA_16816(acc[j], aR[2][0], aR[2][1], aR[2][2], aR[2][3], c0, c1);
            MMA_16816(acc[j], aR[3][0], aR[3][1], aR[3][2], aR[3][3], c2, c3);
        }

        __half* g = gdst[m];
#pragma unroll
        for (int j = 0; j < 8; j++) {
            const int col = j * 8 + (lane & 3) * 2;
            const int head = col >> 5, d = col & 31;
            const size_t adr = ((size_t)(win * HEADS + head) * NN + n0 + w) * HD + d;
            *(__half2*)&g[adr] = __floats2half2_rn(acc[j][0], acc[j][1]);
            *(__half2*)&g[adr + 8 * HD] = __floats2half2_rn(acc[j][2], acc[j][3]);
        }
    }
}

// ---------------------------------------------------------------------------
// Kernel 2: fused flash attention + output projection.
// Grid 1024 = (win, qt).  Block 512 = 16 warps: warps 0-7 head0, 8-15 head1.
// Each warp: 16 queries.  Loop 16 chunks of 64 keys (both heads' K/V staged).
// Epilogue: O -> smem fp16, proj GEMM [128x64]x[64x64], scatter fp32 to y.
// SMEM: 2 buffers x 4 tiles (K0,V0,K1,V1) x 5120B = 40960B; reused for O+Wp.
// ---------------------------------------------------------------------------
#define TILE_B  5120
#define BUF_B   (4 * TILE_B)   // 20480

__global__ __launch_bounds__(512, 1) void attn_proj_kernel(
    const float* __restrict__ Wp,
    float* __restrict__ y)
{
    __shared__ __align__(16) unsigned char sm[2 * BUF_B];   // 40960 B

    const int tid  = threadIdx.x;
    const int wid  = tid >> 5;
    const int lane = tid & 31;
    const int head = wid >> 3;
    const int wq   = wid & 7;

    const int blk = blockIdx.x;
    const int win = blk >> 3;
    const int qt  = blk & 7;
    const int b   = win >> 6;
    const int p   = win & 63;
    const int h   = p * 4 + (qt >> 1);
    const int w0  = (qt & 1) * 128;

    const uint32_t smb = smem_u32(sm);
    const int wh = win * HEADS + head;

    // ---- cooperative K/V loader: 1024 16B-chunks/iter, 2 per thread ----
    const __half* srcp[2];
    uint32_t dsto[2];
    int rowv[2], chv[2];
#pragma unroll
    for (int u = 0; u < 2; u++) {
        const int c = tid + u * 512;
        const int tile = c >> 8;          // 0..3 = K0,V0,K1,V1
        const int hd_ = tile >> 1, kv = tile & 1;
        rowv[u] = (c >> 2) & 63;
        chv[u]  = c & 3;
        srcp[u] = (kv ? g_vh : g_kh) + (size_t)(win * HEADS + hd_) * NN * HD;
        dsto[u] = (uint32_t)tile * TILE_B + (uint32_t)rowv[u] * 80 + (uint32_t)chv[u] * 16;
    }

    // prefetch chunk 0
#pragma unroll
    for (int u = 0; u < 2; u++)
        CP_ASYNC16(smb + dsto[u], (const char*)(srcp[u] + (size_t)rowv[u] * HD + chv[u] * 8));
    CP_COMMIT();

    // ---- Q fragments ----
    const __half* qb = g_qh + (size_t)wh * NN * HD;
    const int qrow = qt * 128 + wq * 16;
    const int grp = lane >> 2;
    const int qd  = (lane & 3) * 2;
    uint32_t qa[8];
#pragma unroll
    for (int kt = 0; kt < 2; kt++) {
        const int d0 = kt * 16;
        qa[kt * 4 + 0] = *(const uint32_t*)&qb[(size_t)(qrow + grp) * HD + d0 + qd];
        qa[kt * 4 + 1] = *(const uint32_t*)&qb[(size_t)(qrow + grp + 8) * HD + d0 + qd];
        qa[kt * 4 + 2] = *(const uint32_t*)&qb[(size_t)(qrow + grp) * HD + d0 + qd + 8];
        qa[kt * 4 + 3] = *(const uint32_t*)&qb[(size_t)(qrow + grp + 8) * HD + d0 + qd + 8];
    }

    float o[4][4];
#pragma unroll
    for (int i = 0; i < 4; i++)
#pragma unroll
        for (int j = 0; j < 4; j++) o[i][j] = 0.f;
    float lacc[4] = {0.f, 0.f, 0.f, 0.f};

    const uint32_t k_off = (uint32_t)(lane & 7) * 80 + (uint32_t)(lane >> 3) * 16;
    const uint32_t v_row = ((uint32_t)((lane >> 3) & 1) * 8 + (uint32_t)(lane & 7)) * 80;
    const uint32_t v_ch  = (uint32_t)((lane >> 4) & 1) * 16;
    const uint32_t ONE2  = 0x3C003C00u;

    for (int kc = 0; kc < 16; kc++) {
        CP_WAIT0();
        __syncthreads();

        if (kc < 15) {
            const uint32_t nbuf = (uint32_t)((kc + 1) & 1) * BUF_B;
#pragma unroll
            for (int u = 0; u < 2; u++)
                CP_ASYNC16(smb + nbuf + dsto[u],
                           (const char*)(srcp[u] + (size_t)((kc + 1) * 64 + rowv[u]) * HD + chv[u] * 8));
            CP_COMMIT();
        }

        const uint32_t smK = smb + (uint32_t)(kc & 1) * BUF_B + (uint32_t)(head * 2) * TILE_B;
        const uint32_t smV = smK + TILE_B;

        // ---- S = Q K^T (16 x 64), log2-domain ----
        float s[8][4];
#pragma unroll
        for (int j = 0; j < 8; j++) {
            s[j][0] = s[j][1] = s[j][2] = s[j][3] = 0.f;
            uint32_t b0, b1, b2, b3;
            LDSM_X4(b0, b1, b2, b3, smK + (uint32_t)(j * 8) * 80 + k_off);
            MMA_16816(s[j], qa[0], qa[1], qa[2], qa[3], b0, b1);
            MMA_16816(s[j], qa[4], qa[5], qa[6], qa[7], b2, b3);
        }

        // ---- P = 2^S to fp16 pairs ----
        uint32_t plo[8], phi[8];
#pragma unroll
        for (int j = 0; j < 8; j++) {
            plo[j] = exp2_h2(s[j][1], s[j][0]);
            phi[j] = exp2_h2(s[j][3], s[j][2]);
        }

        // ---- O += P V, l += P * ones ----
#pragma unroll
        for (int t = 0; t < 4; t++) {
            const uint32_t a0 = plo[2 * t], a1 = phi[2 * t];
            const uint32_t a2 = plo[2 * t + 1], a3 = phi[2 * t + 1];
            const uint32_t vbase = smV + (uint32_t)(t * 16) * 80 + v_row + v_ch;
            MMA_16816(lacc, a0, a1, a2, a3, ONE2, ONE2);
#pragma unroll
            for (int pass = 0; pass < 2; pass++) {
                uint32_t b0, b1, b2, b3;
                LDSM_X4_T(b0, b1, b2, b3, vbase + (uint32_t)pass * 32);
                MMA_16816(o[pass * 2 + 0], a0, a1, a2, a3, b0, b1);
                MMA_16816(o[pass * 2 + 1], a0, a1, a2, a3, b2, b3);
            }
        }
    }

    // ================= epilogue: fused projection =================
    __syncthreads();   // all warps done reading K/V smem

    __half* smO = (__half*)sm;                       // [128][XSTR]
    __half* smW = (__half*)(sm + 128 * XSTR * 2);    // [64][XSTR]

    // O -> smem fp16 (normalized)
    {
        const float inv0 = 1.f / lacc[0];
        const float inv1 = 1.f / lacc[2];
        const int row = wq * 16 + grp;
#pragma unroll
        for (int dt = 0; dt < 4; dt++) {
            const int col = head * HD + dt * 8 + (lane & 3) * 2;
            *(__half2*)&smO[row * XSTR + col] =
                __floats2half2_rn(o[dt][0] * inv0, o[dt][1] * inv0);
            *(__half2*)&smO[(row + 8) * XSTR + col] =
                __floats2half2_rn(o[dt][2] * inv1, o[dt][3] * inv1);
        }
    }
    // Wp -> smem fp16
    for (int i = tid; i < CC * CC; i += 512)
        smW[(i >> 6) * XSTR + (i & 63)] = __float2half(Wp[i]);
    __syncthreads();

    // proj GEMM: warp = 16 token-rows x 32 cols
    {
        const uint32_t smOu = smem_u32(smO);
        const uint32_t smWu = smem_u32(smW);
        const int colhalf = wid >> 3;

        uint32_t aR[4][4];
#pragma unroll
        for (int kt = 0; kt < 4; kt++) {
            uint32_t ad = smOu + (uint32_t)(wq * 16 + (lane & 15)) * (XSTR * 2)
                        + (uint32_t)kt * 32 + (uint32_t)(lane >> 4) * 16;
            LDSM_X4(aR[kt][0], aR[kt][1], aR[kt][2], aR[kt][3], ad);
        }

        const int tokw = w0 + wq * 16 + grp;
#pragma unroll
        for (int j4 = 0; j4 < 4; j4++) {
            const int j = colhalf * 4 + j4;
            float acc[4] = {0.f, 0.f, 0.f, 0.f};
            uint32_t b0, b1, b2, b3, c0, c1, c2, c3;
            const uint32_t wad = smWu + (uint32_t)(j * 8 + (lane & 7)) * (XSTR * 2)
                               + (uint32_t)(lane >> 3) * 16;
            LDSM_X4(b0, b1, b2, b3, wad);
            LDSM_X4(c0, c1, c2, c3, wad + 64);
            MMA_16816(acc, aR[0][0], aR[0][1], aR[0][2], aR[0][3], b0, b1);
            MMA_16816(acc, aR[1][0], aR[1][1], aR[1][2], aR[1][3], b2, b3);
            MMA_16816(acc, aR[2][0], aR[2][1], aR[2][2], aR[2][3], c0, c1);
            MMA_16816(acc, aR[3][0], aR[3][1], aR[3][2], aR[3][3], c2, c3);

            const int col = j * 8 + (lane & 3) * 2;
            const size_t a0 = ((size_t)(b * CC + col) * HH + h) * WW + tokw;
            const size_t a1 = a0 + (size_t)HH * WW;
            y[a0] = acc[0];
            y[a1] = acc[1];
            y[a0 + 8] = acc[2];
            y[a1 + 8] = acc[3];
        }
    }
}

// ---------------------------------------------------------------------------
extern "C" void kernel_launch(void* const* d_in, const int* in_sizes, int n_in,
                              void* d_out, int out_size)
{
    const float* x  = (const float*)d_in[0];
    const float* Wq = (const float*)d_in[1];
    const float* Wk = (const float*)d_in[2];
    const float* Wv = (const float*)d_in[3];
    const float* Wp = (const float*)d_in[4];
    float* y = (float*)d_out;

    qkv_kernel<<<BB * HH * 2, 256>>>(x, Wq, Wk, Wv);
    attn_proj_kernel<<<NWIN * 8, 512>>>(Wp, y);
}

// round 10
// speedup vs baseline: 1.1230x; 1.1230x over previous
#include <cuda_runtime.h>
#include <cuda_fp16.h>
#include <cstdint>
#include <math.h>

// ---------------------------------------------------------------------------
// Problem constants
// ---------------------------------------------------------------------------
#define BB     2
#define CC     64
#define HH     256
#define WW     256
#define HEADS  2
#define HD     32
#define ROWS   4
#define PP     (HH / ROWS)      // 64 windows per image
#define NN     (ROWS * WW)      // 1024 tokens per window
#define NWIN   (BB * PP)        // 128 windows
#define NWH    (NWIN * HEADS)   // 256 window-heads

#define SCALE   0.17677669529663687f   // 1/sqrt(32)
#define LOG2E   1.4426950408889634f

// ---------------------------------------------------------------------------
// Scratch: q,k,v fp16 [wh][n][d] token-major (q pre-scaled by SCALE*LOG2E)
// o: fp16 [win][n][64]
// ---------------------------------------------------------------------------
__device__ __half g_qh[(size_t)NWH * NN * HD];
__device__ __half g_kh[(size_t)NWH * NN * HD];
__device__ __half g_vh[(size_t)NWH * NN * HD];
__device__ __half g_oh[(size_t)NWIN * NN * CC];

__device__ __forceinline__ uint32_t smem_u32(const void* p) {
    uint32_t a;
    asm("{ .reg .u64 t; cvta.to.shared.u64 t, %1; cvt.u32.u64 %0, t; }" : "=r"(a) : "l"(p));
    return a;
}

#define LDSM_X4(r0, r1, r2, r3, addr) \
    asm volatile("ldmatrix.sync.aligned.m8n8.x4.shared.b16 {%0,%1,%2,%3}, [%4];" \
                 : "=r"(r0), "=r"(r1), "=r"(r2), "=r"(r3) : "r"(addr))
#define LDSM_X4_T(r0, r1, r2, r3, addr) \
    asm volatile("ldmatrix.sync.aligned.m8n8.x4.trans.shared.b16 {%0,%1,%2,%3}, [%4];" \
                 : "=r"(r0), "=r"(r1), "=r"(r2), "=r"(r3) : "r"(addr))
#define MMA_16816(d, a0, a1, a2, a3, b0, b1) \
    asm volatile("mma.sync.aligned.m16n8k16.row.col.f32.f16.f16.f32 " \
                 "{%0,%1,%2,%3}, {%4,%5,%6,%7}, {%8,%9}, {%0,%1,%2,%3};" \
                 : "+f"((d)[0]), "+f"((d)[1]), "+f"((d)[2]), "+f"((d)[3]) \
                 : "r"(a0), "r"(a1), "r"(a2), "r"(a3), "r"(b0), "r"(b1))
#define CP_ASYNC16(dst, src) \
    asm volatile("cp.async.ca.shared.global [%0], [%1], 16;" :: "r"(dst), "l"(src))
#define CP_COMMIT()  asm volatile("cp.async.commit_group;" ::: "memory")
#define CP_WAIT0()   asm volatile("cp.async.wait_group 0;" ::: "memory")

__device__ __forceinline__ uint32_t exp2_h2(float hi, float lo) {
    uint32_t t;
    asm("{\n\t.reg .b32 u;\n\tcvt.rn.f16x2.f32 u, %1, %2;\n\tex2.approx.f16x2 %0, u;\n\t}"
        : "=r"(t) : "f"(hi), "f"(lo));
    return t;
}

// ---------------------------------------------------------------------------
// Kernel 1: window-gather + QKV projection, tensor-core GEMM.
// Grid 1024 = (b, h, half-row).  Block 256 = 8 warps; warp owns 16 tokens.
// ---------------------------------------------------------------------------
#define XSTR 72

__global__ __launch_bounds__(256, 2) void qkv_kernel(
    const float* __restrict__ x,
    const float* __restrict__ Wq,
    const float* __restrict__ Wk,
    const float* __restrict__ Wv)
{
    __shared__ __align__(16) __half smX[128 * XSTR];      // 18432 B
    __shared__ __align__(16) __half smW[3 * CC * XSTR];   // 27648 B

    const int blk = blockIdx.x;
    const int b = blk >> 9;
    const int h = (blk >> 1) & 255;
    const int half = blk & 1;
    const int w0 = half * 128;
    const int tid = threadIdx.x;
    const int wid = tid >> 5;
    const int lane = tid & 31;

    {
        const int tk = tid & 127;
        const int c0 = (tid >> 7) * 32;
        const size_t base = ((size_t)(b * CC + c0) * HH + h) * WW + w0 + tk;
#pragma unroll
        for (int c = 0; c < 32; c += 2) {
            float f0 = x[base + (size_t)c * (HH * WW)];
            float f1 = x[base + (size_t)(c + 1) * (HH * WW)];
            *(__half2*)&smX[tk * XSTR + c0 + c] = __floats2half2_rn(f0, f1);
        }
    }
    {
        const float qs = SCALE * LOG2E;
        for (int i = tid; i < 3 * CC * CC; i += 256) {
            const int m = i >> 12, j = (i >> 6) & 63, c = i & 63;
            const float* Wm = (m == 0) ? Wq : (m == 1) ? Wk : Wv;
            const float sc = (m == 0) ? qs : 1.f;
            smW[(m * CC + j) * XSTR + c] = __float2half(Wm[j * CC + c] * sc);
        }
    }
    __syncthreads();

    const uint32_t smXu = smem_u32(smX);
    const uint32_t smWu = smem_u32(smW);

    uint32_t aR[4][4];
#pragma unroll
    for (int kt = 0; kt < 4; kt++) {
        uint32_t ad = smXu + (uint32_t)(wid * 16 + (lane & 15)) * (XSTR * 2)
                    + (uint32_t)kt * 32 + (uint32_t)(lane >> 4) * 16;
        LDSM_X4(aR[kt][0], aR[kt][1], aR[kt][2], aR[kt][3], ad);
    }

    const int p = h >> 2, r = h & 3;
    const int win = b * PP + p;
    const int n0 = r * WW;
    const int grp = lane >> 2;
    const int w = w0 + wid * 16 + grp;

    __half* gdst[3] = {g_qh, g_kh, g_vh};

#pragma unroll 1
    for (int m = 0; m < 3; m++) {
        float acc[8][4];
#pragma unroll
        for (int j = 0; j < 8; j++)
            acc[j][0] = acc[j][1] = acc[j][2] = acc[j][3] = 0.f;

#pragma unroll
        for (int j = 0; j < 8; j++) {
            uint32_t b0, b1, b2, b3, c0, c1, c2, c3;
            const uint32_t wad = smWu + (uint32_t)(m * CC + j * 8 + (lane & 7)) * (XSTR * 2)
                               + (uint32_t)(lane >> 3) * 16;
            LDSM_X4(b0, b1, b2, b3, wad);
            LDSM_X4(c0, c1, c2, c3, wad + 64);
            MMA_16816(acc[j], aR[0][0], aR[0][1], aR[0][2], aR[0][3], b0, b1);
            MMA_16816(acc[j], aR[1][0], aR[1][1], aR[1][2], aR[1][3], b2, b3);
            MMA_16816(acc[j], aR[2][0], aR[2][1], aR[2][2], aR[2][3], c0, c1);
            MMA_16816(acc[j], aR[3][0], aR[3][1], aR[3][2], aR[3][3], c2, c3);
        }

        __half* g = gdst[m];
#pragma unroll
        for (int j = 0; j < 8; j++) {
            const int col = j * 8 + (lane & 3) * 2;
            const int head = col >> 5, d = col & 31;
            const size_t adr = ((size_t)(win * HEADS + head) * NN + n0 + w) * HD + d;
            *(__half2*)&g[adr] = __floats2half2_rn(acc[j][0], acc[j][1]);
            *(__half2*)&g[adr + 8 * HD] = __floats2half2_rn(acc[j][2], acc[j][3]);
        }
    }
}

// ---------------------------------------------------------------------------
// Kernel 2: fp16 mma.sync flash attention, warp = 32 queries (2 m16 tiles).
// Grid 2048 = 256 wh x 8 q-tiles.  Block 128 = 4 warps x 32 queries.
// K fragments loaded once per j, shared by both m-tiles: 16 LDSM : 72 MMA.
// cp.async double-buffered K/V; small CTA -> ~3 CTAs/SM for barrier overlap.
// ---------------------------------------------------------------------------
#define TILE_B  5120               // 64 keys x 80B rows
#define BUF_B   (2 * TILE_B)       // K + V per buffer

__global__ __launch_bounds__(128) void attn_kernel()
{
    __shared__ __align__(16) unsigned char sm[2 * BUF_B];   // 20480 B

    const int tid  = threadIdx.x;
    const int wid  = tid >> 5;
    const int lane = tid & 31;

    const int blk = blockIdx.x;
    const int wh  = blk >> 3;
    const int qt  = blk & 7;

    const uint32_t smb = smem_u32(sm);

    const __half* qb = g_qh + (size_t)wh * NN * HD;
    const __half* kb = g_kh + (size_t)wh * NN * HD;
    const __half* vb = g_vh + (size_t)wh * NN * HD;

    // ---- cooperative K/V loader: 512 16B-chunks/iter, 4 per thread ----
    const __half* srcp[4];
    uint32_t dsto[4];
    int rowv[4], chv[4];
#pragma unroll
    for (int u = 0; u < 4; u++) {
        const int c = tid + u * 128;
        const int tile = c >> 8;          // 0 = K, 1 = V
        rowv[u] = (c >> 2) & 63;
        chv[u]  = c & 3;
        srcp[u] = tile ? vb : kb;
        dsto[u] = (uint32_t)tile * TILE_B + (uint32_t)rowv[u] * 80 + (uint32_t)chv[u] * 16;
    }

    // prefetch chunk 0
#pragma unroll
    for (int u = 0; u < 4; u++)
        CP_ASYNC16(smb + dsto[u], (const char*)(srcp[u] + (size_t)rowv[u] * HD + chv[u] * 8));
    CP_COMMIT();

    // ---- Q fragments: warp owns rows [qrow, qrow+32) ----
    const int qrow = qt * 128 + wid * 32;
    const int grp = lane >> 2;
    const int qd  = (lane & 3) * 2;
    uint32_t qa0[8], qa1[8];
#pragma unroll
    for (int kt = 0; kt < 2; kt++) {
        const int d0 = kt * 16;
        qa0[kt * 4 + 0] = *(const uint32_t*)&qb[(size_t)(qrow + grp) * HD + d0 + qd];
        qa0[kt * 4 + 1] = *(const uint32_t*)&qb[(size_t)(qrow + grp + 8) * HD + d0 + qd];
        qa0[kt * 4 + 2] = *(const uint32_t*)&qb[(size_t)(qrow + grp) * HD + d0 + qd + 8];
        qa0[kt * 4 + 3] = *(const uint32_t*)&qb[(size_t)(qrow + grp + 8) * HD + d0 + qd + 8];
        qa1[kt * 4 + 0] = *(const uint32_t*)&qb[(size_t)(qrow + 16 + grp) * HD + d0 + qd];
        qa1[kt * 4 + 1] = *(const uint32_t*)&qb[(size_t)(qrow + 16 + grp + 8) * HD + d0 + qd];
        qa1[kt * 4 + 2] = *(const uint32_t*)&qb[(size_t)(qrow + 16 + grp) * HD + d0 + qd + 8];
        qa1[kt * 4 + 3] = *(const uint32_t*)&qb[(size_t)(qrow + 16 + grp + 8) * HD + d0 + qd + 8];
    }

    float o0[4][4], o1[4][4];
#pragma unroll
    for (int i = 0; i < 4; i++)
#pragma unroll
        for (int j = 0; j < 4; j++) { o0[i][j] = 0.f; o1[i][j] = 0.f; }
    float lacc0[4] = {0.f, 0.f, 0.f, 0.f};
    float lacc1[4] = {0.f, 0.f, 0.f, 0.f};

    const uint32_t k_off = (uint32_t)(lane & 7) * 80 + (uint32_t)(lane >> 3) * 16;
    const uint32_t v_row = ((uint32_t)((lane >> 3) & 1) * 8 + (uint32_t)(lane & 7)) * 80;
    const uint32_t v_ch  = (uint32_t)((lane >> 4) & 1) * 16;
    const uint32_t ONE2  = 0x3C003C00u;

    for (int kc = 0; kc < 16; kc++) {
        CP_WAIT0();
        __syncthreads();

        if (kc < 15) {
            const uint32_t nbuf = (uint32_t)((kc + 1) & 1) * BUF_B;
#pragma unroll
            for (int u = 0; u < 4; u++)
                CP_ASYNC16(smb + nbuf + dsto[u],
                           (const char*)(srcp[u] + (size_t)((kc + 1) * 64 + rowv[u]) * HD + chv[u] * 8));
            CP_COMMIT();
        }

        const uint32_t smK = smb + (uint32_t)(kc & 1) * BUF_B;
        const uint32_t smV = smK + TILE_B;

        // ---- S = Q K^T for both m-tiles; exp per j (frees s immediately) ----
        uint32_t plo0[8], phi0[8], plo1[8], phi1[8];
#pragma unroll
        for (int j = 0; j < 8; j++) {
            uint32_t b0, b1, b2, b3;
            LDSM_X4(b0, b1, b2, b3, smK + (uint32_t)(j * 8) * 80 + k_off);
            float s0[4] = {0.f, 0.f, 0.f, 0.f};
            float s1[4] = {0.f, 0.f, 0.f, 0.f};
            MMA_16816(s0, qa0[0], qa0[1], qa0[2], qa0[3], b0, b1);
            MMA_16816(s0, qa0[4], qa0[5], qa0[6], qa0[7], b2, b3);
            MMA_16816(s1, qa1[0], qa1[1], qa1[2], qa1[3], b0, b1);
            MMA_16816(s1, qa1[4], qa1[5], qa1[6], qa1[7], b2, b3);
            plo0[j] = exp2_h2(s0[1], s0[0]);
            phi0[j] = exp2_h2(s0[3], s0[2]);
            plo1[j] = exp2_h2(s1[1], s1[0]);
            phi1[j] = exp2_h2(s1[3], s1[2]);
        }

        // ---- O += P V, l += P * ones  (V frags shared by both m-tiles) ----
#pragma unroll
        for (int t = 0; t < 4; t++) {
            const uint32_t a00 = plo0[2 * t], a01 = phi0[2 * t];
            const uint32_t a02 = plo0[2 * t + 1], a03 = phi0[2 * t + 1];
            const uint32_t a10 = plo1[2 * t], a11 = phi1[2 * t];
            const uint32_t a12 = plo1[2 * t + 1], a13 = phi1[2 * t + 1];
            MMA_16816(lacc0, a00, a01, a02, a03, ONE2, ONE2);
            MMA_16816(lacc1, a10, a11, a12, a13, ONE2, ONE2);
            const uint32_t vbase = smV + (uint32_t)(t * 16) * 80 + v_row + v_ch;
#pragma unroll
            for (int pass = 0; pass < 2; pass++) {
                uint32_t b0, b1, b2, b3;
                LDSM_X4_T(b0, b1, b2, b3, vbase + (uint32_t)pass * 32);
                MMA_16816(o0[pass * 2 + 0], a00, a01, a02, a03, b0, b1);
                MMA_16816(o0[pass * 2 + 1], a00, a01, a02, a03, b2, b3);
                MMA_16816(o1[pass * 2 + 0], a10, a11, a12, a13, b0, b1);
                MMA_16816(o1[pass * 2 + 1], a10, a11, a12, a13, b2, b3);
            }
        }
    }

    // ---- normalize and write O (fp16, token-major [win][n][64]) ----
    const int win = wh >> 1, head = wh & 1;
    {
        const float i00 = 1.f / lacc0[0], i01 = 1.f / lacc0[2];
        const float i10 = 1.f / lacc1[0], i11 = 1.f / lacc1[2];
        const int r0 = qrow + grp;
        const int r1 = qrow + 16 + grp;
#pragma unroll
        for (int dt = 0; dt < 4; dt++) {
            const int col = head * HD + dt * 8 + (lane & 3) * 2;
            *(__half2*)&g_oh[((size_t)win * NN + r0) * CC + col] =
                __floats2half2_rn(o0[dt][0] * i00, o0[dt][1] * i00);
            *(__half2*)&g_oh[((size_t)win * NN + r0 + 8) * CC + col] =
                __floats2half2_rn(o0[dt][2] * i01, o0[dt][3] * i01);
            *(__half2*)&g_oh[((size_t)win * NN + r1) * CC + col] =
                __floats2half2_rn(o1[dt][0] * i10, o1[dt][1] * i10);
            *(__half2*)&g_oh[((size_t)win * NN + r1 + 8) * CC + col] =
                __floats2half2_rn(o1[dt][2] * i11, o1[dt][3] * i11);
        }
    }
}

// ---------------------------------------------------------------------------
// Kernel 3: output projection, tensor-core GEMM + scatter to [B, C, H, W].
// Grid 1024; block 256; warp owns 16 tokens.
// ---------------------------------------------------------------------------
__global__ __launch_bounds__(256, 2) void proj_kernel(
    const float* __restrict__ Wp,
    float* __restrict__ y)
{
    __shared__ __align__(16) __half smO[128 * XSTR];   // 18432 B
    __shared__ __align__(16) __half smW[CC * XSTR];    //  9216 B

    const int blk = blockIdx.x;
    const int b = blk >> 9;
    const int h = (blk >> 1) & 255;
    const int half = blk & 1;
    const int w0 = half * 128;
    const int tid = threadIdx.x;
    const int wid = tid >> 5;
    const int lane = tid & 31;

    const int p = h >> 2, r = h & 3;
    const int win = b * PP + p;

    {
        const size_t obase = ((size_t)win * NN + r * WW + w0) * CC;
        for (int i = tid; i < 128 * 8; i += 256) {
            const int row = i >> 3, ch = i & 7;
            uint4 v = *(const uint4*)&g_oh[obase + (size_t)row * CC + ch * 8];
            *(uint4*)&smO[row * XSTR + ch * 8] = v;
        }
        for (int i = tid; i < CC * CC; i += 256)
            smW[(i >> 6) * XSTR + (i & 63)] = __float2half(Wp[i]);
    }
    __syncthreads();

    const uint32_t smOu = smem_u32(smO);
    const uint32_t smWu = smem_u32(smW);

    uint32_t aR[4][4];
#pragma unroll
    for (int kt = 0; kt < 4; kt++) {
        uint32_t ad = smOu + (uint32_t)(wid * 16 + (lane & 15)) * (XSTR * 2)
                    + (uint32_t)kt * 32 + (uint32_t)(lane >> 4) * 16;
        LDSM_X4(aR[kt][0], aR[kt][1], aR[kt][2], aR[kt][3], ad);
    }

    float acc[8][4];
#pragma unroll
    for (int j = 0; j < 8; j++)
        acc[j][0] = acc[j][1] = acc[j][2] = acc[j][3] = 0.f;

#pragma unroll
    for (int j = 0; j < 8; j++) {
        uint32_t b0, b1, b2, b3, c0, c1, c2, c3;
        const uint32_t wad = smWu + (uint32_t)(j * 8 + (lane & 7)) * (XSTR * 2)
                           + (uint32_t)(lane >> 3) * 16;
        LDSM_X4(b0, b1, b2, b3, wad);
        LDSM_X4(c0, c1, c2, c3, wad + 64);
        MMA_16816(acc[j], aR[0][0], aR[0][1], aR[0][2], aR[0][3], b0, b1);
        MMA_16816(acc[j], aR[1][0], aR[1][1], aR[1][2], aR[1][3], b2, b3);
        MMA_16816(acc[j], aR[2][0], aR[2][1], aR[2][2], aR[2][3], c0, c1);
        MMA_16816(acc[j], aR[3][0], aR[3][1], aR[3][2], aR[3][3], c2, c3);
    }

    const int grp = lane >> 2;
    const int w = w0 + wid * 16 + grp;
#pragma unroll
    for (int j = 0; j < 8; j++) {
        const int col = j * 8 + (lane & 3) * 2;
        const size_t a0 = ((size_t)(b * CC + col) * HH + h) * WW + w;
        const size_t a1 = a0 + (size_t)HH * WW;
        y[a0] = acc[j][0];
        y[a1] = acc[j][1];
        y[a0 + 8] = acc[j][2];
        y[a1 + 8] = acc[j][3];
    }
}

// ---------------------------------------------------------------------------
extern "C" void kernel_launch(void* const* d_in, const int* in_sizes, int n_in,
                              void* d_out, int out_size)
{
    const float* x  = (const float*)d_in[0];
    const float* Wq = (const float*)d_in[1];
    const float* Wk = (const float*)d_in[2];
    const float* Wv = (const float*)d_in[3];
    const float* Wp = (const float*)d_in[4];
    float* y = (float*)d_out;

    qkv_kernel<<<BB * HH * 2, 256>>>(x, Wq, Wk, Wv);
    attn_kernel<<<NWH * 8, 128>>>();
    proj_kernel<<<BB * HH * 2, 256>>>(Wp, y);
}

// round 11
// speedup vs baseline: 1.2660x; 1.1273x over previous
#include <cuda_runtime.h>
#include <cuda_fp16.h>
#include <cstdint>
#include <math.h>

// ---------------------------------------------------------------------------
// Problem constants
// ---------------------------------------------------------------------------
#define BB     2
#define CC     64
#define HH     256
#define WW     256
#define HEADS  2
#define HD     32
#define ROWS   4
#define PP     (HH / ROWS)      // 64 windows per image
#define NN     (ROWS * WW)      // 1024 tokens per window
#define NWIN   (BB * PP)        // 128 windows
#define NWH    (NWIN * HEADS)   // 256 window-heads

#define SCALE   0.17677669529663687f   // 1/sqrt(32)
#define LOG2E   1.4426950408889634f

// ---------------------------------------------------------------------------
// Scratch: q,k,v fp16 [wh][n][d] token-major (q pre-scaled by SCALE*LOG2E)
// o: fp16 [win][n][64]
// ---------------------------------------------------------------------------
__device__ __half g_qh[(size_t)NWH * NN * HD];
__device__ __half g_kh[(size_t)NWH * NN * HD];
__device__ __half g_vh[(size_t)NWH * NN * HD];
__device__ __half g_oh[(size_t)NWIN * NN * CC];

__device__ __forceinline__ uint32_t smem_u32(const void* p) {
    uint32_t a;
    asm("{ .reg .u64 t; cvta.to.shared.u64 t, %1; cvt.u32.u64 %0, t; }" : "=r"(a) : "l"(p));
    return a;
}

#define LDSM_X4(r0, r1, r2, r3, addr) \
    asm volatile("ldmatrix.sync.aligned.m8n8.x4.shared.b16 {%0,%1,%2,%3}, [%4];" \
                 : "=r"(r0), "=r"(r1), "=r"(r2), "=r"(r3) : "r"(addr))
#define LDSM_X4_T(r0, r1, r2, r3, addr) \
    asm volatile("ldmatrix.sync.aligned.m8n8.x4.trans.shared.b16 {%0,%1,%2,%3}, [%4];" \
                 : "=r"(r0), "=r"(r1), "=r"(r2), "=r"(r3) : "r"(addr))
#define MMA_16816(d, a0, a1, a2, a3, b0, b1) \
    asm volatile("mma.sync.aligned.m16n8k16.row.col.f32.f16.f16.f32 " \
                 "{%0,%1,%2,%3}, {%4,%5,%6,%7}, {%8,%9}, {%0,%1,%2,%3};" \
                 : "+f"((d)[0]), "+f"((d)[1]), "+f"((d)[2]), "+f"((d)[3]) \
                 : "r"(a0), "r"(a1), "r"(a2), "r"(a3), "r"(b0), "r"(b1))
#define CP_ASYNC16(dst, src) \
    asm volatile("cp.async.ca.shared.global [%0], [%1], 16;" :: "r"(dst), "l"(src))
#define CP_COMMIT()  asm volatile("cp.async.commit_group;" ::: "memory")
#define CP_WAIT0()   asm volatile("cp.async.wait_group 0;" ::: "memory")

__device__ __forceinline__ uint32_t exp2_h2(float hi, float lo) {
    uint32_t t;
    asm("{\n\t.reg .b32 u;\n\tcvt.rn.f16x2.f32 u, %1, %2;\n\tex2.approx.f16x2 %0, u;\n\t}"
        : "=r"(t) : "f"(hi), "f"(lo));
    return t;
}

// ---------------------------------------------------------------------------
// Kernel 1: window-gather + QKV projection, tensor-core GEMM.
// Grid 2048 = (b, h, quarter).  Block 128 = 4 warps; warp owns 16 tokens.
// 4 CTAs/SM for phase-diverse latency hiding.
// ---------------------------------------------------------------------------
#define XSTR 72

__global__ __launch_bounds__(128, 4) void qkv_kernel(
    const float* __restrict__ x,
    const float* __restrict__ Wq,
    const float* __restrict__ Wk,
    const float* __restrict__ Wv)
{
    __shared__ __align__(16) __half smX[64 * XSTR];       //  9216 B
    __shared__ __align__(16) __half smW[3 * CC * XSTR];   // 27648 B

    const int blk = blockIdx.x;
    const int b = blk >> 10;
    const int h = (blk >> 2) & 255;
    const int w0 = (blk & 3) * 64;
    const int tid = threadIdx.x;
    const int wid = tid >> 5;
    const int lane = tid & 31;

    // ---- x tile: 64 tokens x 64 ch -> fp16 token-major ----
    {
        const int tk = tid & 63;
        const int c0 = (tid >> 6) * 32;
        const size_t base = ((size_t)(b * CC + c0) * HH + h) * WW + w0 + tk;
#pragma unroll
        for (int c = 0; c < 32; c += 2) {
            float f0 = x[base + (size_t)c * (HH * WW)];
            float f1 = x[base + (size_t)(c + 1) * (HH * WW)];
            *(__half2*)&smX[tk * XSTR + c0 + c] = __floats2half2_rn(f0, f1);
        }
    }
    // ---- weights (float4 loads): q scaled by SCALE*LOG2E ----
    {
        const float qs = SCALE * LOG2E;
        for (int i = tid; i < 3 * 1024; i += 128) {
            const int m = i >> 10;
            const int r = (i >> 4) & 63, c4 = i & 15;
            const float* Wm = (m == 0) ? Wq : (m == 1) ? Wk : Wv;
            const float sc = (m == 0) ? qs : 1.f;
            float4 wv = ((const float4*)Wm)[r * 16 + c4];
            __half* d = &smW[(m * CC + r) * XSTR + c4 * 4];
            *(__half2*)d       = __floats2half2_rn(wv.x * sc, wv.y * sc);
            *(__half2*)(d + 2) = __floats2half2_rn(wv.z * sc, wv.w * sc);
        }
    }
    __syncthreads();

    const uint32_t smXu = smem_u32(smX);
    const uint32_t smWu = smem_u32(smW);

    uint32_t aR[4][4];
#pragma unroll
    for (int kt = 0; kt < 4; kt++) {
        uint32_t ad = smXu + (uint32_t)(wid * 16 + (lane & 15)) * (XSTR * 2)
                    + (uint32_t)kt * 32 + (uint32_t)(lane >> 4) * 16;
        LDSM_X4(aR[kt][0], aR[kt][1], aR[kt][2], aR[kt][3], ad);
    }

    const int p = h >> 2, r = h & 3;
    const int win = b * PP + p;
    const int n0 = r * WW;
    const int grp = lane >> 2;
    const int w = w0 + wid * 16 + grp;

    __half* gdst[3] = {g_qh, g_kh, g_vh};

#pragma unroll 1
    for (int m = 0; m < 3; m++) {
        float acc[8][4];
#pragma unroll
        for (int j = 0; j < 8; j++)
            acc[j][0] = acc[j][1] = acc[j][2] = acc[j][3] = 0.f;

#pragma unroll
        for (int j = 0; j < 8; j++) {
            uint32_t b0, b1, b2, b3, c0, c1, c2, c3;
            const uint32_t wad = smWu + (uint32_t)(m * CC + j * 8 + (lane & 7)) * (XSTR * 2)
                               + (uint32_t)(lane >> 3) * 16;
            LDSM_X4(b0, b1, b2, b3, wad);
            LDSM_X4(c0, c1, c2, c3, wad + 64);
            MMA_16816(acc[j], aR[0][0], aR[0][1], aR[0][2], aR[0][3], b0, b1);
            MMA_16816(acc[j], aR[1][0], aR[1][1], aR[1][2], aR[1][3], b2, b3);
            MMA_16816(acc[j], aR[2][0], aR[2][1], aR[2][2], aR[2][3], c0, c1);
            MMA_16816(acc[j], aR[3][0], aR[3][1], aR[3][2], aR[3][3], c2, c3);
        }

        __half* g = gdst[m];
#pragma unroll
        for (int j = 0; j < 8; j++) {
            const int col = j * 8 + (lane & 3) * 2;
            const int head = col >> 5, d = col & 31;
            const size_t adr = ((size_t)(win * HEADS + head) * NN + n0 + w) * HD + d;
            *(__half2*)&g[adr] = __floats2half2_rn(acc[j][0], acc[j][1]);
            *(__half2*)&g[adr + 8 * HD] = __floats2half2_rn(acc[j][2], acc[j][3]);
        }
    }
}

// ---------------------------------------------------------------------------
// Kernel 2: fp16 mma.sync flash attention, warp = 32 queries.
// 128-key chunks (two 64-key halves) per barrier round: 8 syncs total.
// Grid 2048 = 256 wh x 8 q-tiles.  Block 128 = 4 warps.
// ---------------------------------------------------------------------------
#define KT_B    10240              // K tile: 128 keys x 80B
#define BUF_B   (2 * KT_B)         // K + V per buffer (20480)

__global__ __launch_bounds__(128) void attn_kernel()
{
    __shared__ __align__(16) unsigned char sm[2 * BUF_B];   // 40960 B

    const int tid  = threadIdx.x;
    const int wid  = tid >> 5;
    const int lane = tid & 31;

    const int blk = blockIdx.x;
    const int wh  = blk >> 3;
    const int qt  = blk & 7;

    const uint32_t smb = smem_u32(sm);

    const __half* qb = g_qh + (size_t)wh * NN * HD;
    const __half* kb = g_kh + (size_t)wh * NN * HD;
    const __half* vb = g_vh + (size_t)wh * NN * HD;

    // ---- cooperative K/V loader: 1024 16B-chunks/iter, 8 per thread ----
    const __half* srcp[8];
    uint32_t dsto[8];
    int rowv[8], chv[8];
#pragma unroll
    for (int u = 0; u < 8; u++) {
        const int c = tid + u * 128;
        const int tile = c >> 9;          // 0 = K, 1 = V
        rowv[u] = (c >> 2) & 127;
        chv[u]  = c & 3;
        srcp[u] = tile ? vb : kb;
        dsto[u] = (uint32_t)tile * KT_B + (uint32_t)rowv[u] * 80 + (uint32_t)chv[u] * 16;
    }

    // prefetch chunk 0 (keys 0..127)
#pragma unroll
    for (int u = 0; u < 8; u++)
        CP_ASYNC16(smb + dsto[u], (const char*)(srcp[u] + (size_t)rowv[u] * HD + chv[u] * 8));
    CP_COMMIT();

    // ---- Q fragments: warp owns rows [qrow, qrow+32) ----
    const int qrow = qt * 128 + wid * 32;
    const int grp = lane >> 2;
    const int qd  = (lane & 3) * 2;
    uint32_t qa0[8], qa1[8];
#pragma unroll
    for (int kt = 0; kt < 2; kt++) {
        const int d0 = kt * 16;
        qa0[kt * 4 + 0] = *(const uint32_t*)&qb[(size_t)(qrow + grp) * HD + d0 + qd];
        qa0[kt * 4 + 1] = *(const uint32_t*)&qb[(size_t)(qrow + grp + 8) * HD + d0 + qd];
        qa0[kt * 4 + 2] = *(const uint32_t*)&qb[(size_t)(qrow + grp) * HD + d0 + qd + 8];
        qa0[kt * 4 + 3] = *(const uint32_t*)&qb[(size_t)(qrow + grp + 8) * HD + d0 + qd + 8];
        qa1[kt * 4 + 0] = *(const uint32_t*)&qb[(size_t)(qrow + 16 + grp) * HD + d0 + qd];
        qa1[kt * 4 + 1] = *(const uint32_t*)&qb[(size_t)(qrow + 16 + grp + 8) * HD + d0 + qd];
        qa1[kt * 4 + 2] = *(const uint32_t*)&qb[(size_t)(qrow + 16 + grp) * HD + d0 + qd + 8];
        qa1[kt * 4 + 3] = *(const uint32_t*)&qb[(size_t)(qrow + 16 + grp + 8) * HD + d0 + qd + 8];
    }

    float o0[4][4], o1[4][4];
#pragma unroll
    for (int i = 0; i < 4; i++)
#pragma unroll
        for (int j = 0; j < 4; j++) { o0[i][j] = 0.f; o1[i][j] = 0.f; }
    float lacc0[4] = {0.f, 0.f, 0.f, 0.f};
    float lacc1[4] = {0.f, 0.f, 0.f, 0.f};

    const uint32_t k_off = (uint32_t)(lane & 7) * 80 + (uint32_t)(lane >> 3) * 16;
    const uint32_t v_row = ((uint32_t)((lane >> 3) & 1) * 8 + (uint32_t)(lane & 7)) * 80;
    const uint32_t v_ch  = (uint32_t)((lane >> 4) & 1) * 16;
    const uint32_t ONE2  = 0x3C003C00u;

    for (int kc = 0; kc < 8; kc++) {
        CP_WAIT0();
        __syncthreads();

        if (kc < 7) {
            const uint32_t nbuf = (uint32_t)((kc + 1) & 1) * BUF_B;
#pragma unroll
            for (int u = 0; u < 8; u++)
                CP_ASYNC16(smb + nbuf + dsto[u],
                           (const char*)(srcp[u] + (size_t)((kc + 1) * 128 + rowv[u]) * HD + chv[u] * 8));
            CP_COMMIT();
        }

        const uint32_t bufb = smb + (uint32_t)(kc & 1) * BUF_B;

#pragma unroll
        for (int half = 0; half < 2; half++) {
            const uint32_t smK = bufb + (uint32_t)half * (64 * 80);
            const uint32_t smV = bufb + KT_B + (uint32_t)half * (64 * 80);

            // ---- S = Q K^T for both m-tiles; exp per j ----
            uint32_t plo0[8], phi0[8], plo1[8], phi1[8];
#pragma unroll
            for (int j = 0; j < 8; j++) {
                uint32_t b0, b1, b2, b3;
                LDSM_X4(b0, b1, b2, b3, smK + (uint32_t)(j * 8) * 80 + k_off);
                float s0[4] = {0.f, 0.f, 0.f, 0.f};
                float s1[4] = {0.f, 0.f, 0.f, 0.f};
                MMA_16816(s0, qa0[0], qa0[1], qa0[2], qa0[3], b0, b1);
                MMA_16816(s0, qa0[4], qa0[5], qa0[6], qa0[7], b2, b3);
                MMA_16816(s1, qa1[0], qa1[1], qa1[2], qa1[3], b0, b1);
                MMA_16816(s1, qa1[4], qa1[5], qa1[6], qa1[7], b2, b3);
                plo0[j] = exp2_h2(s0[1], s0[0]);
                phi0[j] = exp2_h2(s0[3], s0[2]);
                plo1[j] = exp2_h2(s1[1], s1[0]);
                phi1[j] = exp2_h2(s1[3], s1[2]);
            }

            // ---- O += P V, l += P * ones ----
#pragma unroll
            for (int t = 0; t < 4; t++) {
                const uint32_t a00 = plo0[2 * t], a01 = phi0[2 * t];
                const uint32_t a02 = plo0[2 * t + 1], a03 = phi0[2 * t + 1];
                const uint32_t a10 = plo1[2 * t], a11 = phi1[2 * t];
                const uint32_t a12 = plo1[2 * t + 1], a13 = phi1[2 * t + 1];
                MMA_16816(lacc0, a00, a01, a02, a03, ONE2, ONE2);
                MMA_16816(lacc1, a10, a11, a12, a13, ONE2, ONE2);
                const uint32_t vbase = smV + (uint32_t)(t * 16) * 80 + v_row + v_ch;
#pragma unroll
                for (int pass = 0; pass < 2; pass++) {
                    uint32_t b0, b1, b2, b3;
                    LDSM_X4_T(b0, b1, b2, b3, vbase + (uint32_t)pass * 32);
                    MMA_16816(o0[pass * 2 + 0], a00, a01, a02, a03, b0, b1);
                    MMA_16816(o0[pass * 2 + 1], a00, a01, a02, a03, b2, b3);
                    MMA_16816(o1[pass * 2 + 0], a10, a11, a12, a13, b0, b1);
                    MMA_16816(o1[pass * 2 + 1], a10, a11, a12, a13, b2, b3);
                }
            }
        }
    }

    // ---- normalize and write O (fp16, token-major [win][n][64]) ----
    const int win = wh >> 1, head = wh & 1;
    {
        const float i00 = 1.f / lacc0[0], i01 = 1.f / lacc0[2];
        const float i10 = 1.f / lacc1[0], i11 = 1.f / lacc1[2];
        const int r0 = qrow + grp;
        const int r1 = qrow + 16 + grp;
#pragma unroll
        for (int dt = 0; dt < 4; dt++) {
            const int col = head * HD + dt * 8 + (lane & 3) * 2;
            *(__half2*)&g_oh[((size_t)win * NN + r0) * CC + col] =
                __floats2half2_rn(o0[dt][0] * i00, o0[dt][1] * i00);
            *(__half2*)&g_oh[((size_t)win * NN + r0 + 8) * CC + col] =
                __floats2half2_rn(o0[dt][2] * i01, o0[dt][3] * i01);
            *(__half2*)&g_oh[((size_t)win * NN + r1) * CC + col] =
                __floats2half2_rn(o1[dt][0] * i10, o1[dt][1] * i10);
            *(__half2*)&g_oh[((size_t)win * NN + r1 + 8) * CC + col] =
                __floats2half2_rn(o1[dt][2] * i11, o1[dt][3] * i11);
        }
    }
}

// ---------------------------------------------------------------------------
// Kernel 3: output projection, tensor-core GEMM + scatter to [B, C, H, W].
// Grid 2048; block 128 = 4 warps; warp owns 16 tokens.  4 CTAs/SM.
// ---------------------------------------------------------------------------
__global__ __launch_bounds__(128, 4) void proj_kernel(
    const float* __restrict__ Wp,
    float* __restrict__ y)
{
    __shared__ __align__(16) __half smO[64 * XSTR];    // 9216 B
    __shared__ __align__(16) __half smW[CC * XSTR];    // 9216 B

    const int blk = blockIdx.x;
    const int b = blk >> 10;
    const int h = (blk >> 2) & 255;
    const int w0 = (blk & 3) * 64;
    const int tid = threadIdx.x;
    const int wid = tid >> 5;
    const int lane = tid & 31;

    const int p = h >> 2, r = h & 3;
    const int win = b * PP + p;

    {
        const size_t obase = ((size_t)win * NN + r * WW + w0) * CC;
        for (int i = tid; i < 64 * 8; i += 128) {
            const int row = i >> 3, ch = i & 7;
            uint4 v = *(const uint4*)&g_oh[obase + (size_t)row * CC + ch * 8];
            *(uint4*)&smO[row * XSTR + ch * 8] = v;
        }
        for (int i = tid; i < 1024; i += 128) {
            const int rr = i >> 4, c4 = i & 15;
            float4 wv = ((const float4*)Wp)[i];
            __half* d = &smW[rr * XSTR + c4 * 4];
            *(__half2*)d       = __floats2half2_rn(wv.x, wv.y);
            *(__half2*)(d + 2) = __floats2half2_rn(wv.z, wv.w);
        }
    }
    __syncthreads();

    const uint32_t smOu = smem_u32(smO);
    const uint32_t smWu = smem_u32(smW);

    uint32_t aR[4][4];
#pragma unroll
    for (int kt = 0; kt < 4; kt++) {
        uint32_t ad = smOu + (uint32_t)(wid * 16 + (lane & 15)) * (XSTR * 2)
                    + (uint32_t)kt * 32 + (uint32_t)(lane >> 4) * 16;
        LDSM_X4(aR[kt][0], aR[kt][1], aR[kt][2], aR[kt][3], ad);
    }

    float acc[8][4];
#pragma unroll
    for (int j = 0; j < 8; j++)
        acc[j][0] = acc[j][1] = acc[j][2] = acc[j][3] = 0.f;

#pragma unroll
    for (int j = 0; j < 8; j++) {
        uint32_t b0, b1, b2, b3, c0, c1, c2, c3;
        const uint32_t wad = smWu + (uint32_t)(j * 8 + (lane & 7)) * (XSTR * 2)
                           + (uint32_t)(lane >> 3) * 16;
        LDSM_X4(b0, b1, b2, b3, wad);
        LDSM_X4(c0, c1, c2, c3, wad + 64);
        MMA_16816(acc[j], aR[0][0], aR[0][1], aR[0][2], aR[0][3], b0, b1);
        MMA_16816(acc[j], aR[1][0], aR[1][1], aR[1][2], aR[1][3], b2, b3);
        MMA_16816(acc[j], aR[2][0], aR[2][1], aR[2][2], aR[2][3], c0, c1);
        MMA_16816(acc[j], aR[3][0], aR[3][1], aR[3][2], aR[3][3], c2, c3);
    }

    const int grp = lane >> 2;
    const int w = w0 + wid * 16 + grp;
#pragma unroll
    for (int j = 0; j < 8; j++) {
        const int col = j * 8 + (lane & 3) * 2;
        const size_t a0 = ((size_t)(b * CC + col) * HH + h) * WW + w;
        const size_t a1 = a0 + (size_t)HH * WW;
        y[a0] = acc[j][0];
        y[a1] = acc[j][1];
        y[a0 + 8] = acc[j][2];
        y[a1 + 8] = acc[j][3];
    }
}

// ---------------------------------------------------------------------------
extern "C" void kernel_launch(void* const* d_in, const int* in_sizes, int n_in,
                              void* d_out, int out_size)
{
    const float* x  = (const float*)d_in[0];
    const float* Wq = (const float*)d_in[1];
    const float* Wk = (const float*)d_in[2];
    const float* Wv = (const float*)d_in[3];
    const float* Wp = (const float*)d_in[4];
    float* y = (float*)d_out;

    qkv_kernel<<<BB * HH * 4, 128>>>(x, Wq, Wk, Wv);
    attn_kernel<<<NWH * 8, 128>>>();
    proj_kernel<<<BB * HH * 4, 128>>>(Wp, y);
}